// round 1
// baseline (speedup 1.0000x reference)
#include <cuda_runtime.h>

// GaussianLayer: 2D Gaussian "same" conv (25x25, center tap zeroed) over
// src (4,512,512,21) NHWC fp32.  FFT reference == zero-padded direct conv.
// Separable: dst = g_y * (g_x * src) - src   (center weight of full sep = 1).

#define BATCH 4
#define HH    512
#define WW    512
#define CC    21
#define RR    12
#define TAPS  25
#define ROWF  (WW * CC)          /* 10752 floats per (b,y) row        */
#define IMGF  (HH * ROWF)        /* per-batch elements                */
#define TOTALF (BATCH * IMGF)    /* 22,020,096                        */

__device__ float g_W[TAPS];
__device__ float g_tmp[TOTALF];   // 88 MB static scratch (allowed)

__global__ void init_weights_kernel(const float* __restrict__ k) {
    int j = threadIdx.x;
    if (j < TAPS) {
        // row RR of the 25x25 kernel is exp(-(j-12)^2/18); center was zeroed
        // in the 2D kernel, but the separable center weight is 1.0 (we subtract
        // src at the end to account for the zeroed 2D center tap).
        g_W[j] = (j == RR) ? 1.0f : k[RR * TAPS + j];
    }
}

// ---------------- Pass 1: horizontal (over x, stride CC in flat index) -----
// Each thread produces 4 adjacent x outputs for one channel: 28 loads, 100 FMA.
__global__ void __launch_bounds__(256) pass_h_kernel(const float* __restrict__ src) {
    const int PER_ROW = (WW / 4) * CC;              // 2688 threads per (b,y) row
    int tid = blockIdx.x * 256 + threadIdx.x;
    if (tid >= BATCH * HH * PER_ROW) return;

    int row = tid / PER_ROW;                        // b*H + y
    int rem = tid - row * PER_ROW;
    int xg  = rem / CC;
    int c   = rem - xg * CC;
    int x0  = xg * 4;

    const float* rp = src   + (size_t)row * ROWF;
    float*       op = g_tmp + (size_t)row * ROWF;
    int base = x0 * CC + c;

    float w[TAPS];
#pragma unroll
    for (int j = 0; j < TAPS; ++j) w[j] = g_W[j];

    float in[28];
    if (x0 >= RR && x0 + 3 + RR < WW) {
#pragma unroll
        for (int s = 0; s < 28; ++s)
            in[s] = rp[base + (s - RR) * CC];
    } else {
#pragma unroll
        for (int s = 0; s < 28; ++s) {
            int xin = x0 - RR + s;
            in[s] = (xin >= 0 && xin < WW) ? rp[base + (s - RR) * CC] : 0.0f;
        }
    }

    float a0 = 0.f, a1 = 0.f, a2 = 0.f, a3 = 0.f;
#pragma unroll
    for (int j = 0; j < TAPS; ++j) {
        float wj = w[j];
        a0 = fmaf(wj, in[j],     a0);
        a1 = fmaf(wj, in[j + 1], a1);
        a2 = fmaf(wj, in[j + 2], a2);
        a3 = fmaf(wj, in[j + 3], a3);
    }
    op[base]          = a0;
    op[base + CC]     = a1;
    op[base + 2 * CC] = a2;
    op[base + 3 * CC] = a3;
}

// ---------------- Pass 2: vertical (over y, stride ROWF) + subtract src ----
// Each thread produces 4 adjacent y outputs for one flat (x,c) column.
// Consecutive threads -> consecutive flat index: perfectly coalesced loads.
__global__ void __launch_bounds__(256) pass_v_kernel(const float* __restrict__ src,
                                                     float* __restrict__ dst) {
    const int PER_B = (HH / 4) * ROWF;              // 1,376,256 threads per batch
    int tid = blockIdx.x * 256 + threadIdx.x;
    if (tid >= BATCH * PER_B) return;

    int b   = tid / PER_B;
    int rem = tid - b * PER_B;
    int yg  = rem / ROWF;
    int f   = rem - yg * ROWF;
    int y0  = yg * 4;

    const float* tp = g_tmp + (size_t)b * IMGF + f;
    const float* sp = src   + (size_t)b * IMGF + f;
    float*       dp = dst   + (size_t)b * IMGF + f;

    float w[TAPS];
#pragma unroll
    for (int j = 0; j < TAPS; ++j) w[j] = g_W[j];

    float in[28];
    if (y0 >= RR && y0 + 3 + RR < HH) {
#pragma unroll
        for (int s = 0; s < 28; ++s)
            in[s] = tp[(size_t)(y0 - RR + s) * ROWF];
    } else {
#pragma unroll
        for (int s = 0; s < 28; ++s) {
            int yin = y0 - RR + s;
            in[s] = (yin >= 0 && yin < HH) ? tp[(size_t)yin * ROWF] : 0.0f;
        }
    }

    float a0 = 0.f, a1 = 0.f, a2 = 0.f, a3 = 0.f;
#pragma unroll
    for (int j = 0; j < TAPS; ++j) {
        float wj = w[j];
        a0 = fmaf(wj, in[j],     a0);
        a1 = fmaf(wj, in[j + 1], a1);
        a2 = fmaf(wj, in[j + 2], a2);
        a3 = fmaf(wj, in[j + 3], a3);
    }

    // subtract src (accounts for the zeroed 2D center tap)
    a0 -= sp[(size_t)(y0 + 0) * ROWF];
    a1 -= sp[(size_t)(y0 + 1) * ROWF];
    a2 -= sp[(size_t)(y0 + 2) * ROWF];
    a3 -= sp[(size_t)(y0 + 3) * ROWF];

    dp[(size_t)(y0 + 0) * ROWF] = a0;
    dp[(size_t)(y0 + 1) * ROWF] = a1;
    dp[(size_t)(y0 + 2) * ROWF] = a2;
    dp[(size_t)(y0 + 3) * ROWF] = a3;
}

extern "C" void kernel_launch(void* const* d_in, const int* in_sizes, int n_in,
                              void* d_out, int out_size) {
    const float* src = (const float*)d_in[0];
    const float* k   = (const float*)d_in[1];
    float*       dst = (float*)d_out;

    init_weights_kernel<<<1, 32>>>(k);

    const int PER_ROW = (WW / 4) * CC;                    // 2688
    int nthreads_h = BATCH * HH * PER_ROW;                // 5,505,024
    pass_h_kernel<<<(nthreads_h + 255) / 256, 256>>>(src);

    const int PER_B = (HH / 4) * ROWF;
    int nthreads_v = BATCH * PER_B;                       // 5,505,024
    pass_v_kernel<<<(nthreads_v + 255) / 256, 256>>>(src, dst);
}

// round 2
// speedup vs baseline: 1.3225x; 1.3225x over previous
#include <cuda_runtime.h>

// GaussianLayer: 2D Gaussian "same" conv (25x25, center tap zeroed) over
// src (4,512,512,21) NHWC fp32.  dst = g_y * (g_x * src) - src.
// This round: packed fma.rn.f32x2 (FFMA2) in both passes, LDG.64 in pass_v,
// 8 outputs/thread sliding window in pass_h, symmetric packed weights.

#define BATCH 4
#define HH    512
#define WW    512
#define CC    21
#define RR    12
#define TAPS  25
#define ROWF  (WW * CC)          /* 10752 floats per (b,y) row */
#define IMGF  (HH * ROWF)
#define TOTALF (BATCH * IMGF)    /* 22,020,096 */

typedef unsigned long long u64;

__device__ float g_W[TAPS];
__device__ u64   g_W2[13];       // packed (w,w), symmetric: W2[min(n,24-n)]
__device__ float g_tmp[TOTALF];  // 88 MB static scratch

__device__ __forceinline__ u64 pack2(float lo, float hi) {
    u64 r; asm("mov.b64 %0, {%1, %2};" : "=l"(r) : "f"(lo), "f"(hi)); return r;
}
__device__ __forceinline__ void fma2(u64& d, u64 a, u64 b) {
    asm("fma.rn.f32x2 %0, %1, %2, %0;" : "+l"(d) : "l"(a), "l"(b));
}
__device__ __forceinline__ float2 unpack2(u64 v) {
    float2 f; asm("mov.b64 {%0, %1}, %2;" : "=f"(f.x), "=f"(f.y) : "l"(v)); return f;
}

__global__ void init_weights_kernel(const float* __restrict__ k) {
    int j = threadIdx.x;
    if (j < TAPS) {
        // Row RR of the 2D kernel; separable center weight is 1.0 (the zeroed
        // 2D center tap is accounted for by subtracting src at the end).
        float w = (j == RR) ? 1.0f : k[RR * TAPS + j];
        g_W[j] = w;
        if (j <= RR) g_W2[j] = pack2(w, w);
    }
}

// ---------------- Pass 1: horizontal. 8 adjacent x outputs per thread, ------
// scalar sliding window of 32 loads, packed into f32x2 pairs on the fly.
__global__ void __launch_bounds__(256) pass_h_kernel(const float* __restrict__ src) {
    const int PER_ROW = (WW / 8) * CC;              // 1344 threads per (b,y) row
    int tid = blockIdx.x * 256 + threadIdx.x;       // grid sized exactly

    int row = tid / PER_ROW;                        // b*H + y
    int rem = tid - row * PER_ROW;
    int xg  = rem / CC;
    int c   = rem - xg * CC;
    int x0  = xg * 8;

    const float* rp = src   + (size_t)row * ROWF;
    float*       op = g_tmp + (size_t)row * ROWF;
    int base = x0 * CC + c;

    u64 W2[13];
#pragma unroll
    for (int j = 0; j < 13; ++j) W2[j] = g_W2[j];

    float v[32];
    if (x0 >= RR && x0 + 19 < WW) {
#pragma unroll
        for (int s = 0; s < 32; ++s)
            v[s] = rp[base + (s - RR) * CC];
    } else {
#pragma unroll
        for (int s = 0; s < 32; ++s) {
            int xin = x0 - RR + s;
            v[s] = (xin >= 0 && xin < WW) ? rp[base + (s - RR) * CC] : 0.0f;
        }
    }

    // A[m] accumulates outputs (x0+2m, x0+2m+1):
    //   A[m] += (w_n, w_n) * (v[n+2m], v[n+2m+1])
    u64 A[4] = {0ull, 0ull, 0ull, 0ull};
#pragma unroll
    for (int i = 0; i < 31; ++i) {
        u64 P = pack2(v[i], v[i + 1]);
#pragma unroll
        for (int m = 0; m < 4; ++m) {
            int n = i - 2 * m;
            if (n >= 0 && n < TAPS)
                fma2(A[m], W2[n <= RR ? n : 24 - n], P);
        }
    }

#pragma unroll
    for (int m = 0; m < 4; ++m) {
        float2 o = unpack2(A[m]);
        op[base + (2 * m)     * CC] = o.x;
        op[base + (2 * m + 1) * CC] = o.y;
    }
}

// ---------------- Pass 2: vertical + subtract src. Thread = one float2 ------
// column pair x 4 y outputs. All loads LDG.64, perfectly coalesced.
__global__ void __launch_bounds__(256) pass_v_kernel(const float* __restrict__ src,
                                                     float* __restrict__ dst) {
    const int PAIRS = ROWF / 2;                     // 5376 pairs per row
    const int PER_B = (HH / 4) * PAIRS;             // 688,128 threads per batch
    int tid = blockIdx.x * 256 + threadIdx.x;       // grid sized exactly

    int b   = tid / PER_B;
    int rem = tid - b * PER_B;
    int yg  = rem / PAIRS;
    int fp  = rem - yg * PAIRS;
    int y0  = yg * 4;

    size_t off = (size_t)b * IMGF + 2 * (size_t)fp;
    const float* tp = g_tmp + off;
    const float* sp = src   + off;
    float*       dp = dst   + off;

    u64 W2[13];
#pragma unroll
    for (int j = 0; j < 13; ++j) W2[j] = g_W2[j];

    u64 v[28];
    if (y0 >= RR && y0 + 15 < HH) {
#pragma unroll
        for (int s = 0; s < 28; ++s)
            v[s] = *(const u64*)(tp + (size_t)(y0 - RR + s) * ROWF);
    } else {
#pragma unroll
        for (int s = 0; s < 28; ++s) {
            int yin = y0 - RR + s;
            v[s] = (yin >= 0 && yin < HH)
                       ? *(const u64*)(tp + (size_t)yin * ROWF)
                       : 0ull;
        }
    }

    u64 A[4] = {0ull, 0ull, 0ull, 0ull};
#pragma unroll
    for (int n = 0; n < TAPS; ++n) {
        u64 w = W2[n <= RR ? n : 24 - n];
#pragma unroll
        for (int m = 0; m < 4; ++m)
            fma2(A[m], w, v[n + m]);
    }

#pragma unroll
    for (int m = 0; m < 4; ++m) {
        float2 o  = unpack2(A[m]);
        float2 s2 = *(const float2*)(sp + (size_t)(y0 + m) * ROWF);
        float2 r;
        r.x = o.x - s2.x;
        r.y = o.y - s2.y;
        *(float2*)(dp + (size_t)(y0 + m) * ROWF) = r;
    }
}

extern "C" void kernel_launch(void* const* d_in, const int* in_sizes, int n_in,
                              void* d_out, int out_size) {
    const float* src = (const float*)d_in[0];
    const float* k   = (const float*)d_in[1];
    float*       dst = (float*)d_out;

    init_weights_kernel<<<1, 32>>>(k);

    int nthreads_h = BATCH * HH * (WW / 8) * CC;          // 2,752,512
    pass_h_kernel<<<nthreads_h / 256, 256>>>(src);

    int nthreads_v = BATCH * (HH / 4) * (ROWF / 2);       // 2,752,512
    pass_v_kernel<<<nthreads_v / 256, 256>>>(src, dst);
}

// round 3
// speedup vs baseline: 1.6890x; 1.2772x over previous
#include <cuda_runtime.h>
#include <cuda_fp16.h>

// GaussianLayer: 2D Gaussian "same" conv (25x25, center tap zeroed) over
// src (4,512,512,21) NHWC fp32.  dst = g_y * (g_x * src) - src.
// Round 3: fp16 intermediate (44MB, L2-resident), no init kernel,
// pass_v does 8 y-outputs/thread, FFMA2 everywhere.

#define BATCH 4
#define HH    512
#define WW    512
#define CC    21
#define RR    12
#define TAPS  25
#define ROWF  (WW * CC)          /* 10752 floats per (b,y) row */
#define IMGF  (HH * ROWF)
#define TOTALF (BATCH * IMGF)    /* 22,020,096 */

typedef unsigned long long u64;

__device__ __half g_tmp[TOTALF];   // 44 MB fp16 scratch (L2-resident)

__device__ __forceinline__ u64 pack2(float lo, float hi) {
    u64 r; asm("mov.b64 %0, {%1, %2};" : "=l"(r) : "f"(lo), "f"(hi)); return r;
}
__device__ __forceinline__ void fma2(u64& d, u64 a, u64 b) {
    asm("fma.rn.f32x2 %0, %1, %2, %0;" : "+l"(d) : "l"(a), "l"(b));
}
__device__ __forceinline__ float2 unpack2(u64 v) {
    float2 f; asm("mov.b64 {%0, %1}, %2;" : "=f"(f.x), "=f"(f.y) : "l"(v)); return f;
}

// Load the 13 symmetric 1D weights (row RR of the 2D kernel; g[RR]=1 since the
// zeroed 2D center tap is handled by subtracting src at the end).
__device__ __forceinline__ void load_weights(const float* __restrict__ k, u64* W2) {
#pragma unroll
    for (int j = 0; j < 12; ++j) {
        float w = __ldg(k + RR * TAPS + j);
        W2[j] = pack2(w, w);
    }
    W2[12] = pack2(1.0f, 1.0f);
}

// ---------------- Pass 1: horizontal. 8 adjacent x outputs per thread, ------
// scalar sliding window of 32 fp32 loads -> FFMA2 -> 8 fp16 stores.
__global__ void __launch_bounds__(256) pass_h_kernel(const float* __restrict__ src,
                                                     const float* __restrict__ k) {
    const int PER_ROW = (WW / 8) * CC;              // 1344 threads per (b,y) row
    int tid = blockIdx.x * 256 + threadIdx.x;       // grid sized exactly

    int row = tid / PER_ROW;                        // b*H + y
    int rem = tid - row * PER_ROW;
    int xg  = rem / CC;
    int c   = rem - xg * CC;
    int x0  = xg * 8;

    const float* rp = src   + (size_t)row * ROWF;
    __half*      op = g_tmp + (size_t)row * ROWF;
    int base = x0 * CC + c;

    u64 W2[13];
    load_weights(k, W2);

    float v[32];
    if (x0 >= RR && x0 + 19 < WW) {
#pragma unroll
        for (int s = 0; s < 32; ++s)
            v[s] = rp[base + (s - RR) * CC];
    } else {
#pragma unroll
        for (int s = 0; s < 32; ++s) {
            int xin = x0 - RR + s;
            v[s] = (xin >= 0 && xin < WW) ? rp[base + (s - RR) * CC] : 0.0f;
        }
    }

    // A[m] accumulates outputs (x0+2m, x0+2m+1)
    u64 A[4] = {0ull, 0ull, 0ull, 0ull};
#pragma unroll
    for (int i = 0; i < 31; ++i) {
        u64 P = pack2(v[i], v[i + 1]);
#pragma unroll
        for (int m = 0; m < 4; ++m) {
            int n = i - 2 * m;
            if (n >= 0 && n < TAPS)
                fma2(A[m], W2[n <= RR ? n : 24 - n], P);
        }
    }

#pragma unroll
    for (int m = 0; m < 4; ++m) {
        float2 o = unpack2(A[m]);
        op[base + (2 * m)     * CC] = __float2half_rn(o.x);
        op[base + (2 * m + 1) * CC] = __float2half_rn(o.y);
    }
}

// ---------------- Pass 2: vertical + subtract src. Thread = one half2 -------
// column pair x 8 y outputs. Window loads are LDG.32 (half2), coalesced.
__global__ void __launch_bounds__(256) pass_v_kernel(const float* __restrict__ src,
                                                     const float* __restrict__ k,
                                                     float* __restrict__ dst) {
    const int PAIRS = ROWF / 2;                     // 5376 pairs per row
    const int PER_B = (HH / 8) * PAIRS;             // 344,064 threads per batch
    int tid = blockIdx.x * 256 + threadIdx.x;       // grid sized exactly

    int b   = tid / PER_B;
    int rem = tid - b * PER_B;
    int yg  = rem / PAIRS;
    int fp  = rem - yg * PAIRS;
    int y0  = yg * 8;

    size_t off = (size_t)b * IMGF + 2 * (size_t)fp;
    const __half* tp = g_tmp + off;
    const float*  sp = src   + off;
    float*        dp = dst   + off;

    u64 W2[13];
    load_weights(k, W2);

    __half2 v[32];
    if (y0 >= RR && y0 + 19 < HH) {
#pragma unroll
        for (int s = 0; s < 32; ++s)
            v[s] = *(const __half2*)(tp + (size_t)(y0 - RR + s) * ROWF);
    } else {
        const __half2 z = __float2half2_rn(0.0f);
#pragma unroll
        for (int s = 0; s < 32; ++s) {
            int yin = y0 - RR + s;
            v[s] = (yin >= 0 && yin < HH)
                       ? *(const __half2*)(tp + (size_t)yin * ROWF)
                       : z;
        }
    }

    u64 A[8] = {0ull, 0ull, 0ull, 0ull, 0ull, 0ull, 0ull, 0ull};
#pragma unroll
    for (int s = 0; s < 32; ++s) {
        float2 f = __half22float2(v[s]);
        u64 P = pack2(f.x, f.y);
#pragma unroll
        for (int m = 0; m < 8; ++m) {
            int n = s - m;
            if (n >= 0 && n < TAPS)
                fma2(A[m], W2[n <= RR ? n : 24 - n], P);
        }
    }

#pragma unroll
    for (int m = 0; m < 8; ++m) {
        float2 o  = unpack2(A[m]);
        float2 s2 = *(const float2*)(sp + (size_t)(y0 + m) * ROWF);
        float2 r;
        r.x = o.x - s2.x;
        r.y = o.y - s2.y;
        *(float2*)(dp + (size_t)(y0 + m) * ROWF) = r;
    }
}

extern "C" void kernel_launch(void* const* d_in, const int* in_sizes, int n_in,
                              void* d_out, int out_size) {
    const float* src = (const float*)d_in[0];
    const float* k   = (const float*)d_in[1];
    float*       dst = (float*)d_out;

    int nthreads_h = BATCH * HH * (WW / 8) * CC;          // 2,752,512
    pass_h_kernel<<<nthreads_h / 256, 256>>>(src, k);

    int nthreads_v = BATCH * (HH / 8) * (ROWF / 2);       // 1,376,256
    pass_v_kernel<<<nthreads_v / 256, 256>>>(src, k, dst);
}